// round 10
// baseline (speedup 1.0000x reference)
#include <cuda_runtime.h>
#include <math.h>
#include <float.h>

#define NN     1500
#define GIN    32
#define GOUT   8
#define HID    128
#define CAP    128          // max nnz per combined-adjacency row (mean ~60)
#define LALPHA 0.2f
#define USTR   68           // us smem row stride (floats)
#define VSTR   132          // vs smem row stride (floats)

typedef unsigned long long ull;

// ---------------- scratch (device globals) ----------------------------------
__device__ int      g_cnt[NN];
__device__ unsigned g_cols[NN * CAP];       // col | (a==2 ? bit31 : 0); zero-init
__device__ float    g_enc[NN * GOUT];       // final GAT output
__device__ float    g_h[2][NN * GOUT];      // ping-pong transformed feats
__device__ float    g_fsrc[2][NN];
__device__ float    g_fdst[2][NN];
__device__ float    g_uT[HID * NN + 64];    // transposed [h][i]
__device__ float    g_vT[HID * NN + 64];
__device__ float    g_cu[NN];               // 0.5*sum_h c_h u_ih + fc2_b
__device__ float    g_cv[NN];               // 0.5*sum_h c_h v_jh
__device__ float    g_cw;                   // 0.5*sum_h c_h w_h

// ---------------- f32x2 packed helpers --------------------------------------
__device__ __forceinline__ ull f2_pack(float lo, float hi) {
    ull r; asm("mov.b64 %0, {%1, %2};" : "=l"(r) : "f"(lo), "f"(hi)); return r;
}
__device__ __forceinline__ void f2_unpack(float& lo, float& hi, ull p) {
    asm("mov.b64 {%0, %1}, %2;" : "=f"(lo), "=f"(hi) : "l"(p));
}
__device__ __forceinline__ ull f2_add(ull a, ull b) {
    ull r; asm("add.rn.f32x2 %0, %1, %2;" : "=l"(r) : "l"(a), "l"(b)); return r;
}
__device__ __forceinline__ ull f2_fma(ull a, ull b, ull c) {
    ull r; asm("fma.rn.f32x2 %0, %1, %2, %3;" : "=l"(r) : "l"(a), "l"(b), "l"(c)); return r;
}

// ---------------- 1) sparse adjacency build + layer-0 transform -------------
__global__ void k_build(const float4* __restrict__ geo,
                        const float4* __restrict__ sem,
                        const float* __restrict__ feats,
                        const float* __restrict__ W0,
                        const float* __restrict__ a0) {
    const int i = blockIdx.x;
    const int tid = threadIdx.x;             // 128
    const float4* g = geo + (size_t)i * (NN / 4);
    const float4* s = sem + (size_t)i * (NN / 4);

    int c = 0;
#pragma unroll
    for (int k = 0; k < 3; k++) {
        int f = tid + k * 128;
        if (f < NN / 4) {
            float4 a = g[f], b = s[f];
            c += (a.x + b.x > 0.f) + (a.y + b.y > 0.f) +
                 (a.z + b.z > 0.f) + (a.w + b.w > 0.f);
        }
    }
    int lane = tid & 31, wid = tid >> 5;
    int x = c;
#pragma unroll
    for (int o = 1; o < 32; o <<= 1) {
        int y = __shfl_up_sync(0xFFFFFFFFu, x, o);
        if (lane >= o) x += y;
    }
    __shared__ int wsum[4];
    if (lane == 31) wsum[wid] = x;
    __syncthreads();
    int base = 0;
    for (int k = 0; k < wid; k++) base += wsum[k];
    int off = base + x - c;
    if (tid == 0) {
        int tot = wsum[0] + wsum[1] + wsum[2] + wsum[3];
        g_cnt[i] = min(tot, CAP);
    }
    unsigned* dst = g_cols + (size_t)i * CAP;
#pragma unroll
    for (int k = 0; k < 3; k++) {
        int f = tid + k * 128;
        if (f < NN / 4) {
            float4 a = g[f], b = s[f];
            float v[4] = {a.x + b.x, a.y + b.y, a.z + b.z, a.w + b.w};
#pragma unroll
            for (int c4 = 0; c4 < 4; c4++) {
                if (v[c4] > 0.f) {
                    if (off < CAP)
                        dst[off] = (unsigned)(f * 4 + c4) |
                                   (v[c4] >= 1.5f ? 0x80000000u : 0u);
                    off++;
                }
            }
        }
    }

    // fused layer-0 transform
    if (tid < GOUT) {
        float acc = 0.f;
#pragma unroll
        for (int k = 0; k < GIN; k++)
            acc = fmaf(feats[i * GIN + k], W0[k * GOUT + tid], acc);
        g_h[0][i * GOUT + tid] = acc;
        float fs = acc * a0[tid];
        float fd = acc * a0[GOUT + tid];
#pragma unroll
        for (int o = 4; o > 0; o >>= 1) {
            fs += __shfl_xor_sync(0x000000FFu, fs, o);
            fd += __shfl_xor_sync(0x000000FFu, fd, o);
        }
        if (tid == 0) { g_fsrc[0][i] = fs; g_fdst[0][i] = fd; }
    }
}

// ---------------- 2) sparse GAT layer (warp per row) -------------------------
// uint4 cols load, hoisted gathers; non-LAST fuses next-layer transform;
// LAST stores enc + computes CU/CV/CW (register-only u,v — NO scatter writes).
template <bool LAST>
__global__ void k_gats(int hsrc, int hdst,
                       const float* __restrict__ Wn,
                       const float* __restrict__ an,
                       const float* __restrict__ fc1_w,
                       const float* __restrict__ fc1_b,
                       const float* __restrict__ fc2_w,
                       const float* __restrict__ fc2_b) {
    const int lane = threadIdx.x & 31;
    const int i = blockIdx.x * 4 + (threadIdx.x >> 5);
    if (i >= NN) return;

    const float fsrc = g_fsrc[hsrc][i];
    const float* __restrict__ fdst = g_fdst[hsrc];
    const float* __restrict__ hbuf = g_h[hsrc];
    const int cnt = g_cnt[i];
    const unsigned* __restrict__ cols = g_cols + (size_t)i * CAP;

    const uint4 pc4 = *reinterpret_cast<const uint4*>(cols + lane * 4);
    unsigned pc[4] = {pc4.x, pc4.y, pc4.z, pc4.w};
    int   jj[4];
    float av[4];
#pragma unroll
    for (int t = 0; t < 4; t++) {
        jj[t] = (int)(pc[t] & 0x7FFFFFFFu);
        av[t] = (pc[t] & 0x80000000u) ? 2.f : 1.f;
    }
    float fd[4];
#pragma unroll
    for (int t = 0; t < 4; t++) fd[t] = fdst[jj[t]];
    float4 h0[4], h1[4];
#pragma unroll
    for (int t = 0; t < 4; t++) {
        const float4* hp = reinterpret_cast<const float4*>(hbuf + jj[t] * GOUT);
        h0[t] = hp[0]; h1[t] = hp[1];
    }

    float e[4];
    float m = -FLT_MAX;
#pragma unroll
    for (int t = 0; t < 4; t++) {
        float tt = fsrc + fd[t];
        float le = (tt > 0.f ? tt : LALPHA * tt) * av[t];
        e[t] = (lane * 4 + t < cnt) ? le : -FLT_MAX;
        m = fmaxf(m, e[t]);
    }
#pragma unroll
    for (int o = 16; o > 0; o >>= 1)
        m = fmaxf(m, __shfl_xor_sync(0xFFFFFFFFu, m, o));

    float s = 0.f, acc[GOUT];
#pragma unroll
    for (int q = 0; q < GOUT; q++) acc[q] = 0.f;
#pragma unroll
    for (int t = 0; t < 4; t++) {
        float p = expf(e[t] - m);
        s += p;
        acc[0] = fmaf(p, h0[t].x, acc[0]); acc[1] = fmaf(p, h0[t].y, acc[1]);
        acc[2] = fmaf(p, h0[t].z, acc[2]); acc[3] = fmaf(p, h0[t].w, acc[3]);
        acc[4] = fmaf(p, h1[t].x, acc[4]); acc[5] = fmaf(p, h1[t].y, acc[5]);
        acc[6] = fmaf(p, h1[t].z, acc[6]); acc[7] = fmaf(p, h1[t].w, acc[7]);
    }
#pragma unroll
    for (int o = 16; o > 0; o >>= 1) {
        s += __shfl_xor_sync(0xFFFFFFFFu, s, o);
#pragma unroll
        for (int q = 0; q < GOUT; q++)
            acc[q] += __shfl_xor_sync(0xFFFFFFFFu, acc[q], o);
    }

    float inv = 1.f / s;
    float enc[GOUT];
#pragma unroll
    for (int q = 0; q < GOUT; q++) {
        float v = acc[q] * inv;
        enc[q] = (v > 0.f) ? v : expm1f(v);   // elu; all lanes hold full enc
    }

    if (!LAST) {
        if (lane < GOUT) {
            float hn = 0.f;
#pragma unroll
            for (int k = 0; k < GOUT; k++)
                hn = fmaf(enc[k], Wn[k * GOUT + lane], hn);
            g_h[hdst][i * GOUT + lane] = hn;
            float fs = hn * an[lane];
            float fdv = hn * an[GOUT + lane];
#pragma unroll
            for (int o = 4; o > 0; o >>= 1) {
                fs  += __shfl_xor_sync(0x000000FFu, fs, o);
                fdv += __shfl_xor_sync(0x000000FFu, fdv, o);
            }
            if (lane == 0) { g_fsrc[hdst][i] = fs; g_fdst[hdst][i] = fdv; }
        }
    } else {
        if (lane < GOUT) g_enc[i * GOUT + lane] = enc[lane];
        // CU/CV: register-only u,v per 4 hidden channels per lane
        float cu = 0.f, cv = 0.f;
#pragma unroll
        for (int k = 0; k < 4; k++) {
            int h = lane + 32 * k;
            float u = fc1_b[h], v = 0.f;
#pragma unroll
            for (int q = 0; q < GOUT; q++) {
                u = fmaf(enc[q], fc1_w[q * HID + h], u);
                v = fmaf(enc[q], fc1_w[(GOUT + q) * HID + h], v);
            }
            float ch = fc2_w[h];
            cu = fmaf(ch, u, cu);
            cv = fmaf(ch, v, cv);
        }
#pragma unroll
        for (int o = 16; o > 0; o >>= 1) {
            cu += __shfl_xor_sync(0xFFFFFFFFu, cu, o);
            cv += __shfl_xor_sync(0xFFFFFFFFu, cv, o);
        }
        if (lane == 0) {
            g_cu[i] = 0.5f * cu + fc2_b[0];
            g_cv[i] = 0.5f * cv;
        }
        if (i == 0) {
            float cwp = 0.f;
#pragma unroll
            for (int k = 0; k < 4; k++) {
                int h = lane + 32 * k;
                cwp = fmaf(fc2_w[h], fc1_w[16 * HID + h], cwp);
            }
#pragma unroll
            for (int o = 16; o > 0; o >>= 1)
                cwp += __shfl_xor_sync(0xFFFFFFFFu, cwp, o);
            if (lane == 0) g_cw = 0.5f * cwp;
        }
    }
}

// ---------------- 3) rank-split precompute, coalesced transposed writes -----
__global__ void k_prep(const float* __restrict__ fc1_w,
                       const float* __restrict__ fc1_b) {
    const int h = blockIdx.x;                 // 0..127
    float wu[GOUT], wv[GOUT];
#pragma unroll
    for (int k = 0; k < GOUT; k++) {
        wu[k] = fc1_w[k * HID + h];
        wv[k] = fc1_w[(GOUT + k) * HID + h];
    }
    const float bu = fc1_b[h];
    for (int i = threadIdx.x; i < NN; i += blockDim.x) {
        const float4* ep = reinterpret_cast<const float4*>(g_enc + i * GOUT);
        float4 e0 = ep[0], e1 = ep[1];
        float ev[8] = {e0.x, e0.y, e0.z, e0.w, e1.x, e1.y, e1.z, e1.w};
        float u = bu, v = 0.f;
#pragma unroll
        for (int k = 0; k < GOUT; k++) {
            u = fmaf(ev[k], wu[k], u);
            v = fmaf(ev[k], wv[k], v);
        }
        g_uT[h * NN + i] = u;
        g_vT[h * NN + i] = v;
    }
}

// ---------------- 4) pair MLP --------------------------------------------------
// out = CU_i + CV_j + CW*d + sum_h 0.5*c_h*|u+v+d*w|   (+b folded into CU)
// CTA 64i x 128j, 256 threads, 4x8 pairs/thread. Each thread owns j-columns
// {4jg..4jg+3} and {64+4jg..64+4jg+3}: LDS.128 v-reads are 16B-strided across
// lanes (granules 0..7 per phase) -> conflict-free, and read as ulonglong2
// (pre-packed pairs, no MOVs).
__global__ __launch_bounds__(256, 2) void k_pairs(const float* __restrict__ dist,
                                                  const float* __restrict__ fc1_w,
                                                  const float* __restrict__ fc2_w,
                                                  float* __restrict__ out) {
    extern __shared__ __align__(16) char smem_raw[];
    float*  us  = reinterpret_cast<float*>(smem_raw);        // [HID][USTR]
    float*  vs  = us + HID * USTR;                           // [HID][VSTR]
    float2* wcs = reinterpret_cast<float2*>(vs + HID * VSTR);// [HID] (w, .5c)
    float*  cus = reinterpret_cast<float*>(wcs + HID);       // [64]
    float*  cvs = cus + 64;                                  // [128]

    const int tid = threadIdx.x;
    const int i0 = blockIdx.y * 64;
    const int j0 = blockIdx.x * 128;

    for (int idx = tid; idx < HID * 16; idx += 256) {
        int h = idx >> 4, c = idx & 15;
        *reinterpret_cast<float4*>(us + h * USTR + 4 * c) =
            *reinterpret_cast<const float4*>(g_uT + (size_t)h * NN + i0 + 4 * c);
    }
    for (int idx = tid; idx < HID * 32; idx += 256) {
        int h = idx >> 5, c = idx & 31;
        *reinterpret_cast<float4*>(vs + h * VSTR + 4 * c) =
            *reinterpret_cast<const float4*>(g_vT + (size_t)h * NN + j0 + 4 * c);
    }
    if (tid < HID)
        wcs[tid] = make_float2(fc1_w[16 * HID + tid], 0.5f * fc2_w[tid]);
    if (tid < 64)
        cus[tid] = g_cu[min(i0 + tid, NN - 1)];
    else if (tid < 192)
        cvs[tid - 64] = g_cv[min(j0 + tid - 64, NN - 1)];
    const float cw = g_cw;
    __syncthreads();

    const int jg = tid & 15;                 // j group: cols 4jg..+3, 64+4jg..+3
    const int ig = tid >> 4;                 // i group: 4 rows
    const int gi  = i0 + 4 * ig;
    const int gjA = j0 + 4 * jg;
    const int gjB = gjA + 64;
    const bool cA = gjA + 3 < NN;
    const bool cB = gjB + 3 < NN;

    ull D[4][4];
#pragma unroll
    for (int r = 0; r < 4; r++) {
        const float4 dz = make_float4(0.f, 0.f, 0.f, 0.f);
        bool rv = (gi + r) < NN;
        float4 da = (rv && cA) ? *reinterpret_cast<const float4*>(dist + (size_t)(gi + r) * NN + gjA) : dz;
        float4 db = (rv && cB) ? *reinterpret_cast<const float4*>(dist + (size_t)(gi + r) * NN + gjB) : dz;
        D[r][0] = f2_pack(da.x, da.y); D[r][1] = f2_pack(da.z, da.w);
        D[r][2] = f2_pack(db.x, db.y); D[r][3] = f2_pack(db.z, db.w);
    }

    ull acc[4][4];
#pragma unroll
    for (int r = 0; r < 4; r++)
#pragma unroll
        for (int q = 0; q < 4; q++) acc[r][q] = 0;

    const ull SMASK = 0x7FFFFFFF7FFFFFFFull;

#pragma unroll 2
    for (int h = 0; h < HID; h++) {
        const float4 u4 = *reinterpret_cast<const float4*>(us + h * USTR + 4 * ig);
        const ulonglong2 va = *reinterpret_cast<const ulonglong2*>(vs + h * VSTR + 4 * jg);
        const ulonglong2 vb = *reinterpret_cast<const ulonglong2*>(vs + h * VSTR + 64 + 4 * jg);
        const float2 wc = wcs[h];
        const ull w2 = f2_pack(wc.x, wc.x);
        const ull c2 = f2_pack(wc.y, wc.y);
        ull uu[4] = {f2_pack(u4.x, u4.x), f2_pack(u4.y, u4.y),
                     f2_pack(u4.z, u4.z), f2_pack(u4.w, u4.w)};
        ull vv[4] = {va.x, va.y, vb.x, vb.y};
#pragma unroll
        for (int r = 0; r < 4; r++) {
#pragma unroll
            for (int q = 0; q < 4; q++) {
                ull p = f2_fma(D[r][q], w2, f2_add(uu[r], vv[q]));
                acc[r][q] = f2_fma(c2, p & SMASK, acc[r][q]);
            }
        }
    }

    const ull cw2 = f2_pack(cw, cw);
#pragma unroll
    for (int r = 0; r < 4; r++) {
        if (gi + r < NN) {
            const float cur = cus[4 * ig + r];
            float res[8];
#pragma unroll
            for (int q = 0; q < 4; q++) {
                int cb = (q < 2) ? (4 * jg + 2 * q) : (64 + 4 * jg + 2 * (q - 2));
                ull cuv = f2_pack(cur + cvs[cb], cur + cvs[cb + 1]);
                ull t = f2_add(acc[r][q], f2_fma(D[r][q], cw2, cuv));
                f2_unpack(res[2 * q], res[2 * q + 1], t);
            }
            float* o = out + (size_t)(gi + r) * NN;
            if (cA)
                *reinterpret_cast<float4*>(o + gjA) =
                    make_float4(res[0], res[1], res[2], res[3]);
            if (cB)
                *reinterpret_cast<float4*>(o + gjB) =
                    make_float4(res[4], res[5], res[6], res[7]);
        }
    }
}

// ---------------- launch ------------------------------------------------------
extern "C" void kernel_launch(void* const* d_in, const int* in_sizes, int n_in,
                              void* d_out, int out_size) {
    const float* geo      = (const float*)d_in[0];
    const float* sem      = (const float*)d_in[1];
    const float* features = (const float*)d_in[2];
    // d_in[3] = region_pairs (int64) — exact meshgrid order, implicit indexing.
    const float* dist     = (const float*)d_in[4];
    const float* W0       = (const float*)d_in[5];
    const float* W1       = (const float*)d_in[6];
    const float* W2       = (const float*)d_in[7];
    const float* a0       = (const float*)d_in[8];
    const float* a1       = (const float*)d_in[9];
    const float* a2       = (const float*)d_in[10];
    const float* fc1_w    = (const float*)d_in[11];
    const float* fc1_b    = (const float*)d_in[12];
    const float* fc2_w    = (const float*)d_in[13];
    const float* fc2_b    = (const float*)d_in[14];
    float* out            = (float*)d_out;

    const int smem_pairs = (HID * USTR + HID * VSTR) * 4 + HID * 8 + 192 * 4;
    cudaFuncSetAttribute(k_pairs, cudaFuncAttributeMaxDynamicSharedMemorySize,
                         smem_pairs);

    k_build<<<NN, 128>>>((const float4*)geo, (const float4*)sem,
                         features, W0, a0);
    k_gats<false><<<(NN + 3) / 4, 128>>>(0, 1, W1, a1, nullptr, nullptr, nullptr, nullptr);
    k_gats<false><<<(NN + 3) / 4, 128>>>(1, 0, W2, a2, nullptr, nullptr, nullptr, nullptr);
    k_gats<true><<<(NN + 3) / 4, 128>>>(0, 1, nullptr, nullptr,
                                        fc1_w, fc1_b, fc2_w, fc2_b);
    k_prep<<<HID, 256>>>(fc1_w, fc1_b);

    dim3 grid((NN + 127) / 128, (NN + 63) / 64);
    k_pairs<<<grid, 256, smem_pairs>>>(dist, fc1_w, fc2_w, out);
}

// round 11
// speedup vs baseline: 1.0339x; 1.0339x over previous
#include <cuda_runtime.h>
#include <math.h>
#include <float.h>

#define NN     1500
#define GIN    32
#define GOUT   8
#define HID    128
#define CAP    128          // max nnz per combined-adjacency row (mean ~60)
#define LALPHA 0.2f
#define USTR   68           // us smem row stride (floats)
#define VSTR   132          // vs smem row stride (floats)
#define G3BLK  375          // k_gat3 blocks (375*4 warps = 1500 rows)

typedef unsigned long long ull;

// ---------------- scratch (device globals) ----------------------------------
__device__ int      g_cnt[NN];
__device__ unsigned g_cols[NN * CAP];       // col | (a==2 ? bit31 : 0); zero-init
__device__ float    g_enc[NN * GOUT];       // final GAT output
__device__ float    g_h[2][NN * GOUT];      // ping-pong transformed feats
__device__ float    g_fsrc[2][NN];
__device__ float    g_fdst[2][NN];
__device__ float    g_uT[HID * NN + 64];    // transposed [h][i]
__device__ float    g_vT[HID * NN + 64];
__device__ float    g_cu[NN];               // 0.5*sum_h c_h u_ih + fc2_b
__device__ float    g_cv[NN];               // 0.5*sum_h c_h v_jh
__device__ float    g_cw;                   // 0.5*sum_h c_h w_h
__device__ int          g_bcnt;             // zero-init; self-restoring
__device__ volatile int g_bsense;           // zero-init; 2 toggles/launch

// ---------------- sense-reversing grid barrier (single-wave grid) -----------
__device__ __forceinline__ void gridbar(int sense) {
    __syncthreads();
    if (threadIdx.x == 0) {
        __threadfence();
        if (atomicAdd(&g_bcnt, 1) == G3BLK - 1) {
            g_bcnt = 0;
            __threadfence();
            g_bsense = sense;
        } else {
            while (g_bsense != sense) { }
        }
        __threadfence();
    }
    __syncthreads();
}

// ---------------- f32x2 packed helpers --------------------------------------
__device__ __forceinline__ ull f2_pack(float lo, float hi) {
    ull r; asm("mov.b64 %0, {%1, %2};" : "=l"(r) : "f"(lo), "f"(hi)); return r;
}
__device__ __forceinline__ void f2_unpack(float& lo, float& hi, ull p) {
    asm("mov.b64 {%0, %1}, %2;" : "=f"(lo), "=f"(hi) : "l"(p));
}
__device__ __forceinline__ ull f2_add(ull a, ull b) {
    ull r; asm("add.rn.f32x2 %0, %1, %2;" : "=l"(r) : "l"(a), "l"(b)); return r;
}
__device__ __forceinline__ ull f2_fma(ull a, ull b, ull c) {
    ull r; asm("fma.rn.f32x2 %0, %1, %2, %3;" : "=l"(r) : "l"(a), "l"(b), "l"(c)); return r;
}

// ---------------- 1) sparse adjacency build + layer-0 transform -------------
__global__ void k_build(const float4* __restrict__ geo,
                        const float4* __restrict__ sem,
                        const float* __restrict__ feats,
                        const float* __restrict__ W0,
                        const float* __restrict__ a0) {
    const int i = blockIdx.x;
    const int tid = threadIdx.x;             // 128
    const float4* g = geo + (size_t)i * (NN / 4);
    const float4* s = sem + (size_t)i * (NN / 4);

    int c = 0;
#pragma unroll
    for (int k = 0; k < 3; k++) {
        int f = tid + k * 128;
        if (f < NN / 4) {
            float4 a = g[f], b = s[f];
            c += (a.x + b.x > 0.f) + (a.y + b.y > 0.f) +
                 (a.z + b.z > 0.f) + (a.w + b.w > 0.f);
        }
    }
    int lane = tid & 31, wid = tid >> 5;
    int x = c;
#pragma unroll
    for (int o = 1; o < 32; o <<= 1) {
        int y = __shfl_up_sync(0xFFFFFFFFu, x, o);
        if (lane >= o) x += y;
    }
    __shared__ int wsum[4];
    if (lane == 31) wsum[wid] = x;
    __syncthreads();
    int base = 0;
    for (int k = 0; k < wid; k++) base += wsum[k];
    int off = base + x - c;
    if (tid == 0) {
        int tot = wsum[0] + wsum[1] + wsum[2] + wsum[3];
        g_cnt[i] = min(tot, CAP);
    }
    unsigned* dst = g_cols + (size_t)i * CAP;
#pragma unroll
    for (int k = 0; k < 3; k++) {
        int f = tid + k * 128;
        if (f < NN / 4) {
            float4 a = g[f], b = s[f];
            float v[4] = {a.x + b.x, a.y + b.y, a.z + b.z, a.w + b.w};
#pragma unroll
            for (int c4 = 0; c4 < 4; c4++) {
                if (v[c4] > 0.f) {
                    if (off < CAP)
                        dst[off] = (unsigned)(f * 4 + c4) |
                                   (v[c4] >= 1.5f ? 0x80000000u : 0u);
                    off++;
                }
            }
        }
    }

    // fused layer-0 transform
    if (tid < GOUT) {
        float acc = 0.f;
#pragma unroll
        for (int k = 0; k < GIN; k++)
            acc = fmaf(feats[i * GIN + k], W0[k * GOUT + tid], acc);
        g_h[0][i * GOUT + tid] = acc;
        float fs = acc * a0[tid];
        float fd = acc * a0[GOUT + tid];
#pragma unroll
        for (int o = 4; o > 0; o >>= 1) {
            fs += __shfl_xor_sync(0x000000FFu, fs, o);
            fd += __shfl_xor_sync(0x000000FFu, fd, o);
        }
        if (tid == 0) { g_fsrc[0][i] = fs; g_fdst[0][i] = fd; }
    }
}

// ---------------- 2) GAT row body (warp per row) -----------------------------
template <bool LAST>
__device__ __forceinline__ void gats_row(int i, int lane, int hsrc, int hdst,
                                         const float* __restrict__ Wn,
                                         const float* __restrict__ an,
                                         const float* __restrict__ fc1_w,
                                         const float* __restrict__ fc1_b,
                                         const float* __restrict__ fc2_w,
                                         const float* __restrict__ fc2_b) {
    const float fsrc = g_fsrc[hsrc][i];
    const float* __restrict__ fdst = g_fdst[hsrc];
    const float* __restrict__ hbuf = g_h[hsrc];
    const int cnt = g_cnt[i];
    const unsigned* __restrict__ cols = g_cols + (size_t)i * CAP;

    const uint4 pc4 = *reinterpret_cast<const uint4*>(cols + lane * 4);
    unsigned pc[4] = {pc4.x, pc4.y, pc4.z, pc4.w};
    int   jj[4];
    float av[4];
#pragma unroll
    for (int t = 0; t < 4; t++) {
        jj[t] = (int)(pc[t] & 0x7FFFFFFFu);
        av[t] = (pc[t] & 0x80000000u) ? 2.f : 1.f;
    }
    float fd[4];
#pragma unroll
    for (int t = 0; t < 4; t++) fd[t] = fdst[jj[t]];
    float4 h0[4], h1[4];
#pragma unroll
    for (int t = 0; t < 4; t++) {
        const float4* hp = reinterpret_cast<const float4*>(hbuf + jj[t] * GOUT);
        h0[t] = hp[0]; h1[t] = hp[1];
    }

    float e[4];
    float m = -FLT_MAX;
#pragma unroll
    for (int t = 0; t < 4; t++) {
        float tt = fsrc + fd[t];
        float le = (tt > 0.f ? tt : LALPHA * tt) * av[t];
        e[t] = (lane * 4 + t < cnt) ? le : -FLT_MAX;
        m = fmaxf(m, e[t]);
    }
#pragma unroll
    for (int o = 16; o > 0; o >>= 1)
        m = fmaxf(m, __shfl_xor_sync(0xFFFFFFFFu, m, o));

    float s = 0.f, acc[GOUT];
#pragma unroll
    for (int q = 0; q < GOUT; q++) acc[q] = 0.f;
#pragma unroll
    for (int t = 0; t < 4; t++) {
        float p = expf(e[t] - m);
        s += p;
        acc[0] = fmaf(p, h0[t].x, acc[0]); acc[1] = fmaf(p, h0[t].y, acc[1]);
        acc[2] = fmaf(p, h0[t].z, acc[2]); acc[3] = fmaf(p, h0[t].w, acc[3]);
        acc[4] = fmaf(p, h1[t].x, acc[4]); acc[5] = fmaf(p, h1[t].y, acc[5]);
        acc[6] = fmaf(p, h1[t].z, acc[6]); acc[7] = fmaf(p, h1[t].w, acc[7]);
    }
#pragma unroll
    for (int o = 16; o > 0; o >>= 1) {
        s += __shfl_xor_sync(0xFFFFFFFFu, s, o);
#pragma unroll
        for (int q = 0; q < GOUT; q++)
            acc[q] += __shfl_xor_sync(0xFFFFFFFFu, acc[q], o);
    }

    float inv = 1.f / s;
    float enc[GOUT];
#pragma unroll
    for (int q = 0; q < GOUT; q++) {
        float v = acc[q] * inv;
        enc[q] = (v > 0.f) ? v : expm1f(v);   // elu; all lanes hold full enc
    }

    if (!LAST) {
        if (lane < GOUT) {
            float hn = 0.f;
#pragma unroll
            for (int k = 0; k < GOUT; k++)
                hn = fmaf(enc[k], Wn[k * GOUT + lane], hn);
            g_h[hdst][i * GOUT + lane] = hn;
            float fs = hn * an[lane];
            float fdv = hn * an[GOUT + lane];
#pragma unroll
            for (int o = 4; o > 0; o >>= 1) {
                fs  += __shfl_xor_sync(0x000000FFu, fs, o);
                fdv += __shfl_xor_sync(0x000000FFu, fdv, o);
            }
            if (lane == 0) { g_fsrc[hdst][i] = fs; g_fdst[hdst][i] = fdv; }
        }
    } else {
        if (lane < GOUT) g_enc[i * GOUT + lane] = enc[lane];
        float cu = 0.f, cv = 0.f;
#pragma unroll
        for (int k = 0; k < 4; k++) {
            int h = lane + 32 * k;
            float u = fc1_b[h], v = 0.f;
#pragma unroll
            for (int q = 0; q < GOUT; q++) {
                u = fmaf(enc[q], fc1_w[q * HID + h], u);
                v = fmaf(enc[q], fc1_w[(GOUT + q) * HID + h], v);
            }
            float ch = fc2_w[h];
            cu = fmaf(ch, u, cu);
            cv = fmaf(ch, v, cv);
        }
#pragma unroll
        for (int o = 16; o > 0; o >>= 1) {
            cu += __shfl_xor_sync(0xFFFFFFFFu, cu, o);
            cv += __shfl_xor_sync(0xFFFFFFFFu, cv, o);
        }
        if (lane == 0) {
            g_cu[i] = 0.5f * cu + fc2_b[0];
            g_cv[i] = 0.5f * cv;
        }
        if (i == 0) {
            float cwp = 0.f;
#pragma unroll
            for (int k = 0; k < 4; k++) {
                int h = lane + 32 * k;
                cwp = fmaf(fc2_w[h], fc1_w[16 * HID + h], cwp);
            }
#pragma unroll
            for (int o = 16; o > 0; o >>= 1)
                cwp += __shfl_xor_sync(0xFFFFFFFFu, cwp, o);
            if (lane == 0) g_cw = 0.5f * cwp;
        }
    }
}

// ---------------- 3) merged 3-layer GAT kernel (single wave, 2 barriers) ----
__global__ __launch_bounds__(128, 1) void k_gat3(
        const float* __restrict__ W1, const float* __restrict__ a1,
        const float* __restrict__ W2, const float* __restrict__ a2,
        const float* __restrict__ fc1_w, const float* __restrict__ fc1_b,
        const float* __restrict__ fc2_w, const float* __restrict__ fc2_b) {
    const int lane = threadIdx.x & 31;
    const int i = blockIdx.x * 4 + (threadIdx.x >> 5);   // one row per warp

    gats_row<false>(i, lane, 0, 1, W1, a1, nullptr, nullptr, nullptr, nullptr);
    gridbar(1);
    gats_row<false>(i, lane, 1, 0, W2, a2, nullptr, nullptr, nullptr, nullptr);
    gridbar(0);
    gats_row<true>(i, lane, 0, 1, nullptr, nullptr, fc1_w, fc1_b, fc2_w, fc2_b);
}

// ---------------- 4) rank-split precompute, coalesced transposed writes -----
__global__ void k_prep(const float* __restrict__ fc1_w,
                       const float* __restrict__ fc1_b) {
    const int h = blockIdx.x;                 // 0..127
    float wu[GOUT], wv[GOUT];
#pragma unroll
    for (int k = 0; k < GOUT; k++) {
        wu[k] = fc1_w[k * HID + h];
        wv[k] = fc1_w[(GOUT + k) * HID + h];
    }
    const float bu = fc1_b[h];
    for (int i = threadIdx.x; i < NN; i += blockDim.x) {
        const float4* ep = reinterpret_cast<const float4*>(g_enc + i * GOUT);
        float4 e0 = ep[0], e1 = ep[1];
        float ev[8] = {e0.x, e0.y, e0.z, e0.w, e1.x, e1.y, e1.z, e1.w};
        float u = bu, v = 0.f;
#pragma unroll
        for (int k = 0; k < GOUT; k++) {
            u = fmaf(ev[k], wu[k], u);
            v = fmaf(ev[k], wv[k], v);
        }
        g_uT[h * NN + i] = u;
        g_vT[h * NN + i] = v;
    }
}

// ---------------- 5) pair MLP --------------------------------------------------
// out = CU_i + CV_j + CW*d + sum_h 0.5*c_h*|u+v+d*w|   (+b folded into CU)
__global__ __launch_bounds__(256, 2) void k_pairs(const float* __restrict__ dist,
                                                  const float* __restrict__ fc1_w,
                                                  const float* __restrict__ fc2_w,
                                                  float* __restrict__ out) {
    extern __shared__ __align__(16) char smem_raw[];
    float*  us  = reinterpret_cast<float*>(smem_raw);        // [HID][USTR]
    float*  vs  = us + HID * USTR;                           // [HID][VSTR]
    float2* wcs = reinterpret_cast<float2*>(vs + HID * VSTR);// [HID] (w, .5c)
    float*  cus = reinterpret_cast<float*>(wcs + HID);       // [64]
    float*  cvs = cus + 64;                                  // [128]

    const int tid = threadIdx.x;
    const int i0 = blockIdx.y * 64;
    const int j0 = blockIdx.x * 128;

    for (int idx = tid; idx < HID * 16; idx += 256) {
        int h = idx >> 4, c = idx & 15;
        *reinterpret_cast<float4*>(us + h * USTR + 4 * c) =
            *reinterpret_cast<const float4*>(g_uT + (size_t)h * NN + i0 + 4 * c);
    }
    for (int idx = tid; idx < HID * 32; idx += 256) {
        int h = idx >> 5, c = idx & 31;
        *reinterpret_cast<float4*>(vs + h * VSTR + 4 * c) =
            *reinterpret_cast<const float4*>(g_vT + (size_t)h * NN + j0 + 4 * c);
    }
    if (tid < HID)
        wcs[tid] = make_float2(fc1_w[16 * HID + tid], 0.5f * fc2_w[tid]);
    if (tid < 64)
        cus[tid] = g_cu[min(i0 + tid, NN - 1)];
    else if (tid < 192)
        cvs[tid - 64] = g_cv[min(j0 + tid - 64, NN - 1)];
    const float cw = g_cw;
    __syncthreads();

    const int jg = tid & 15;                 // j cols {4jg..+3} and {64+4jg..+3}
    const int ig = tid >> 4;                 // i group: 4 rows
    const int gi  = i0 + 4 * ig;
    const int gjA = j0 + 4 * jg;
    const int gjB = gjA + 64;
    const bool cA = gjA + 3 < NN;
    const bool cB = gjB + 3 < NN;

    ull D[4][4];
#pragma unroll
    for (int r = 0; r < 4; r++) {
        const float4 dz = make_float4(0.f, 0.f, 0.f, 0.f);
        bool rv = (gi + r) < NN;
        float4 da = (rv && cA) ? *reinterpret_cast<const float4*>(dist + (size_t)(gi + r) * NN + gjA) : dz;
        float4 db = (rv && cB) ? *reinterpret_cast<const float4*>(dist + (size_t)(gi + r) * NN + gjB) : dz;
        D[r][0] = f2_pack(da.x, da.y); D[r][1] = f2_pack(da.z, da.w);
        D[r][2] = f2_pack(db.x, db.y); D[r][3] = f2_pack(db.z, db.w);
    }

    ull acc[4][4];
#pragma unroll
    for (int r = 0; r < 4; r++)
#pragma unroll
        for (int q = 0; q < 4; q++) acc[r][q] = 0;

    const ull SMASK = 0x7FFFFFFF7FFFFFFFull;

#pragma unroll 2
    for (int h = 0; h < HID; h++) {
        const float4 u4 = *reinterpret_cast<const float4*>(us + h * USTR + 4 * ig);
        const ulonglong2 va = *reinterpret_cast<const ulonglong2*>(vs + h * VSTR + 4 * jg);
        const ulonglong2 vb = *reinterpret_cast<const ulonglong2*>(vs + h * VSTR + 64 + 4 * jg);
        const float2 wc = wcs[h];
        const ull w2 = f2_pack(wc.x, wc.x);
        const ull c2 = f2_pack(wc.y, wc.y);
        ull uu[4] = {f2_pack(u4.x, u4.x), f2_pack(u4.y, u4.y),
                     f2_pack(u4.z, u4.z), f2_pack(u4.w, u4.w)};
        ull vv[4] = {va.x, va.y, vb.x, vb.y};
#pragma unroll
        for (int r = 0; r < 4; r++) {
#pragma unroll
            for (int q = 0; q < 4; q++) {
                ull p = f2_fma(D[r][q], w2, f2_add(uu[r], vv[q]));
                acc[r][q] = f2_fma(c2, p & SMASK, acc[r][q]);
            }
        }
    }

    const ull cw2 = f2_pack(cw, cw);
#pragma unroll
    for (int r = 0; r < 4; r++) {
        if (gi + r < NN) {
            const float cur = cus[4 * ig + r];
            float res[8];
#pragma unroll
            for (int q = 0; q < 4; q++) {
                int cb = (q < 2) ? (4 * jg + 2 * q) : (64 + 4 * jg + 2 * (q - 2));
                ull cuv = f2_pack(cur + cvs[cb], cur + cvs[cb + 1]);
                ull t = f2_add(acc[r][q], f2_fma(D[r][q], cw2, cuv));
                f2_unpack(res[2 * q], res[2 * q + 1], t);
            }
            float* o = out + (size_t)(gi + r) * NN;
            if (cA)
                *reinterpret_cast<float4*>(o + gjA) =
                    make_float4(res[0], res[1], res[2], res[3]);
            if (cB)
                *reinterpret_cast<float4*>(o + gjB) =
                    make_float4(res[4], res[5], res[6], res[7]);
        }
    }
}

// ---------------- launch ------------------------------------------------------
extern "C" void kernel_launch(void* const* d_in, const int* in_sizes, int n_in,
                              void* d_out, int out_size) {
    const float* geo      = (const float*)d_in[0];
    const float* sem      = (const float*)d_in[1];
    const float* features = (const float*)d_in[2];
    // d_in[3] = region_pairs (int64) — exact meshgrid order, implicit indexing.
    const float* dist     = (const float*)d_in[4];
    const float* W0       = (const float*)d_in[5];
    const float* W1       = (const float*)d_in[6];
    const float* W2       = (const float*)d_in[7];
    const float* a0       = (const float*)d_in[8];
    const float* a1       = (const float*)d_in[9];
    const float* a2       = (const float*)d_in[10];
    const float* fc1_w    = (const float*)d_in[11];
    const float* fc1_b    = (const float*)d_in[12];
    const float* fc2_w    = (const float*)d_in[13];
    const float* fc2_b    = (const float*)d_in[14];
    float* out            = (float*)d_out;

    const int smem_pairs = (HID * USTR + HID * VSTR) * 4 + HID * 8 + 192 * 4;
    cudaFuncSetAttribute(k_pairs, cudaFuncAttributeMaxDynamicSharedMemorySize,
                         smem_pairs);

    k_build<<<NN, 128>>>((const float4*)geo, (const float4*)sem,
                         features, W0, a0);
    k_gat3<<<G3BLK, 128>>>(W1, a1, W2, a2, fc1_w, fc1_b, fc2_w, fc2_b);
    k_prep<<<HID, 256>>>(fc1_w, fc1_b);

    dim3 grid((NN + 127) / 128, (NN + 63) / 64);
    k_pairs<<<grid, 256, smem_pairs>>>(dist, fc1_w, fc2_w, out);
}